// round 6
// baseline (speedup 1.0000x reference)
#include <cuda_runtime.h>

#define NN 10000
#define NE 320000
#define HID 128
#define SME_FLOATS 27264
#define SMN_FLOATS 24768

__device__ float g_hA[NN * HID];
__device__ float g_hB[NN * HID];
__device__ float g_x[NN * 3];
__device__ float g_vel[NN * 3];
__device__ float g_aggx[NN * 3];
__device__ float g_aggh[NN * HID];
__device__ float g_cnt[NN];

__device__ __forceinline__ float siluf(float v) {
    return v * __fdividef(1.f, 1.f + __expf(-v));
}
__device__ __forceinline__ float sigf(float v) {
    return __fdividef(1.f, 1.f + __expf(-v));
}

__device__ __forceinline__ unsigned long long pack2(float v) {
    unsigned long long r;
    asm("mov.b64 %0, {%1, %1};" : "=l"(r) : "f"(v));
    return r;
}
__device__ __forceinline__ void unpack2(unsigned long long p, float& a, float& b) {
    asm("mov.b64 {%0, %1}, %2;" : "=f"(a), "=f"(b) : "l"(p));
}
__device__ __forceinline__ void ffma2(unsigned long long& d, unsigned long long a,
                                      unsigned long long b) {
    asm("fma.rn.f32x2 %0, %1, %2, %0;" : "+l"(d) : "l"(a), "l"(b));
}

// 64 rows x 128 cols GEMM, 128 threads, each thread 16 edges x 4 cols (f32x2
// pairs along edges). A transposed+swizzled in SMEM:
// A[k][e] at sA[k*64 + ((e + 4*((k>>2)&15)) & 63)].
// W double-buffered through sW (2 x 4096 floats), register prefetch, one
// barrier per 32-k chunk.
__device__ __forceinline__ void gemm64(const float* sA, float* sW,
                                       const float* __restrict__ gW,
                                       int K, int Kpad, float acc[16][4]) {
    const int tid = threadIdx.x, tx = tid & 31, ty = tid >> 5;
    unsigned long long a2[8][4];
#pragma unroll
    for (int p = 0; p < 8; p++)
#pragma unroll
        for (int j = 0; j < 4; j++) a2[p][j] = 0ULL;
    const float4* __restrict__ gW4 = (const float4*)gW;
    const int nch = Kpad >> 5;
    float4 r[8];
#pragma unroll
    for (int i = 0; i < 8; i++) {
        int f = tid + i * 128;
        int rr = f >> 5;
        r[i] = (rr < K) ? gW4[rr * 32 + (f & 31)] : make_float4(0.f, 0.f, 0.f, 0.f);
    }
#pragma unroll
    for (int i = 0; i < 8; i++) ((float4*)sW)[tid + i * 128] = r[i];
    for (int ci = 0; ci < nch; ci++) {
        __syncthreads();
        const int kb = ci << 5;
        const float* buf = sW + ((ci & 1) << 12);
        const bool more = (ci + 1 < nch);
        if (more) {
#pragma unroll
            for (int i = 0; i < 8; i++) {
                int f = tid + i * 128;
                int rr = kb + 32 + (f >> 5);
                r[i] = (rr < K) ? gW4[rr * 32 + (f & 31)]
                                : make_float4(0.f, 0.f, 0.f, 0.f);
            }
        }
#pragma unroll 4
        for (int kk = 0; kk < 32; kk++) {
            int k = kb + kk;
            int rot = ((k >> 2) & 15) << 2;
            const float* ar = sA + k * 64;
            int base = 16 * ty + rot;
            ulonglong2 a0 = *(const ulonglong2*)(ar + (base & 63));
            ulonglong2 a1 = *(const ulonglong2*)(ar + ((base + 4) & 63));
            ulonglong2 a2l = *(const ulonglong2*)(ar + ((base + 8) & 63));
            ulonglong2 a3 = *(const ulonglong2*)(ar + ((base + 12) & 63));
            float4 w = *(const float4*)(buf + kk * 128 + 4 * tx);
            unsigned long long w0 = pack2(w.x), w1 = pack2(w.y);
            unsigned long long w2 = pack2(w.z), w3 = pack2(w.w);
            ffma2(a2[0][0], a0.x, w0); ffma2(a2[0][1], a0.x, w1);
            ffma2(a2[0][2], a0.x, w2); ffma2(a2[0][3], a0.x, w3);
            ffma2(a2[1][0], a0.y, w0); ffma2(a2[1][1], a0.y, w1);
            ffma2(a2[1][2], a0.y, w2); ffma2(a2[1][3], a0.y, w3);
            ffma2(a2[2][0], a1.x, w0); ffma2(a2[2][1], a1.x, w1);
            ffma2(a2[2][2], a1.x, w2); ffma2(a2[2][3], a1.x, w3);
            ffma2(a2[3][0], a1.y, w0); ffma2(a2[3][1], a1.y, w1);
            ffma2(a2[3][2], a1.y, w2); ffma2(a2[3][3], a1.y, w3);
            ffma2(a2[4][0], a2l.x, w0); ffma2(a2[4][1], a2l.x, w1);
            ffma2(a2[4][2], a2l.x, w2); ffma2(a2[4][3], a2l.x, w3);
            ffma2(a2[5][0], a2l.y, w0); ffma2(a2[5][1], a2l.y, w1);
            ffma2(a2[5][2], a2l.y, w2); ffma2(a2[5][3], a2l.y, w3);
            ffma2(a2[6][0], a3.x, w0); ffma2(a2[6][1], a3.x, w1);
            ffma2(a2[6][2], a3.x, w2); ffma2(a2[6][3], a3.x, w3);
            ffma2(a2[7][0], a3.y, w0); ffma2(a2[7][1], a3.y, w1);
            ffma2(a2[7][2], a3.y, w2); ffma2(a2[7][3], a3.y, w3);
        }
        if (more) {
            float* nb = sW + (((ci + 1) & 1) << 12);
#pragma unroll
            for (int i = 0; i < 8; i++) ((float4*)nb)[tid + i * 128] = r[i];
        }
    }
#pragma unroll
    for (int p = 0; p < 8; p++)
#pragma unroll
        for (int j = 0; j < 4; j++) unpack2(a2[p][j], acc[2 * p][j], acc[2 * p + 1][j]);
    __syncthreads();
}

// Write acc (+bias, silu) transposed into sA rows baseRow..baseRow+127.
__device__ __forceinline__ void store_out64(float* sA, int baseRow, float acc[16][4],
                                            const float* __restrict__ bias) {
    const int tid = threadIdx.x, tx = tid & 31, ty = tid >> 5;
#pragma unroll
    for (int j = 0; j < 4; j++) {
        int c = 4 * tx + j;
        float b = bias[c];
        int rot = ((c >> 2) & 15) << 2;
        float* rp = sA + (baseRow + c) * 64;
#pragma unroll
        for (int g = 0; g < 4; g++) {
            float4 v;
            v.x = siluf(acc[4 * g + 0][j] + b);
            v.y = siluf(acc[4 * g + 1][j] + b);
            v.z = siluf(acc[4 * g + 2][j] + b);
            v.w = siluf(acc[4 * g + 3][j] + b);
            *(float4*)(rp + ((16 * ty + 4 * g + rot) & 63)) = v;
        }
    }
}

__global__ void k_setup(const float* __restrict__ h_in, const float* __restrict__ x_in,
                        const float* __restrict__ vel_in, const float* __restrict__ emb_w,
                        const float* __restrict__ emb_b) {
    int i = blockIdx.x * blockDim.x + threadIdx.x;
    if (i < NN * 3) { g_x[i] = x_in[i]; g_vel[i] = vel_in[i]; }
    if (i < NN) g_cnt[i] = 0.f;
    if (i < NN * HID) {
        int n = i >> 7, c = i & 127;
        float s = emb_b[c];
#pragma unroll
        for (int k = 0; k < 6; k++) s += h_in[n * 6 + k] * emb_w[k * HID + c];
        g_hA[i] = s;
    }
}

__global__ void k_count(const int* __restrict__ edges) {
    int e = blockIdx.x * blockDim.x + threadIdx.x;
    if (e < NE) atomicAdd(&g_cnt[edges[e]], 1.f);
}

__global__ void k_zero() {
    int i = blockIdx.x * blockDim.x + threadIdx.x;
    if (i < NN * 3) g_aggx[i] = 0.f;
    if (i < NN * HID) g_aggh[i] = 0.f;
}

__global__ void __launch_bounds__(128, 2) k_edge(
    int cur, const float* __restrict__ ea, const int* __restrict__ edges,
    const float* __restrict__ ew1, const float* __restrict__ eb1,
    const float* __restrict__ ew2, const float* __restrict__ eb2,
    const float* __restrict__ aw, const float* __restrict__ ab,
    const float* __restrict__ cw1, const float* __restrict__ cb1,
    const float* __restrict__ cw2) {
    extern __shared__ float sm[];
    float* sA = sm;                    // 288 rows x 64
    float* sW = sm + 18432;            // 2 x 4096 (double buffer)
    float* sCD = sm + 26624;           // 192
    float* sWv = sm + 26816;           // 64
    float* sAw = sm + 26880;           // 128
    float* sCw2 = sm + 27008;          // 128
    int* sRow = (int*)(sm + 27136);    // 64
    int* sCol = (int*)(sm + 27200);    // 64
    const float* hb = cur ? g_hB : g_hA;
    const int tid = threadIdx.x, tx = tid & 31, ty = tid >> 5;
    const int e0 = blockIdx.x * 64;

    if (tid < 128) { sAw[tid] = aw[tid]; sCw2[tid] = cw2[tid]; }
    if (tid < 64) {
        int e = e0 + tid;
        int r = edges[e], c = edges[NE + e];
        sRow[tid] = r; sCol[tid] = c;
        float dx = g_x[r * 3] - g_x[c * 3];
        float dy = g_x[r * 3 + 1] - g_x[c * 3 + 1];
        float dz = g_x[r * 3 + 2] - g_x[c * 3 + 2];
        sCD[tid * 3] = dx; sCD[tid * 3 + 1] = dy; sCD[tid * 3 + 2] = dz;
        sA[256 * 64 + tid] = dx * dx + dy * dy + dz * dz;  // rot=0 rows 256..258
        sA[257 * 64 + tid] = ea[e * 2];
        sA[258 * 64 + tid] = ea[e * 2 + 1];
    }
    for (int i = tid; i < 29 * 64; i += 128) sA[259 * 64 + i] = 0.f;
    __syncthreads();
    for (int it = tid; it < 2048; it += 128) {  // h[row] -> rows 0..127
        int e = it & 63, q = it >> 6;
        float4 v = *(const float4*)(hb + sRow[e] * HID + 4 * q);
        int p = (e + ((q & 15) << 2)) & 63;
        int kb = 4 * q * 64;
        sA[kb + p] = v.x; sA[kb + 64 + p] = v.y;
        sA[kb + 128 + p] = v.z; sA[kb + 192 + p] = v.w;
    }
    for (int it = tid; it < 2048; it += 128) {  // h[col] -> rows 128..255
        int e = it & 63, q = it >> 6;
        float4 v = *(const float4*)(hb + sCol[e] * HID + 4 * q);
        int p = (e + ((q & 15) << 2)) & 63;
        int kb = (128 + 4 * q) * 64;
        sA[kb + p] = v.x; sA[kb + 64 + p] = v.y;
        sA[kb + 128 + p] = v.z; sA[kb + 192 + p] = v.w;
    }

    float acc[16][4];
    // GEMM1: t1 = silu(e_in @ ew1 + eb1) -> rows 0..127
    gemm64(sA, sW, ew1, 259, 288, acc);
    store_out64(sA, 0, acc, eb1);
    // GEMM2: m = silu(t1 @ ew2 + eb2), attention gate fused -> rows 128..255
    gemm64(sA, sW, ew2, 128, 128, acc);
    {
        float attp[16];
#pragma unroll
        for (int e = 0; e < 16; e++) attp[e] = 0.f;
#pragma unroll
        for (int j = 0; j < 4; j++) {
            int c = 4 * tx + j;
            float b = eb2[c], wA = sAw[c];
#pragma unroll
            for (int e = 0; e < 16; e++) {
                acc[e][j] = siluf(acc[e][j] + b);
                attp[e] += acc[e][j] * wA;
            }
        }
        float abv = ab[0];
#pragma unroll
        for (int e = 0; e < 16; e++) {
            float v = attp[e];
            v += __shfl_xor_sync(0xffffffffu, v, 16);
            v += __shfl_xor_sync(0xffffffffu, v, 8);
            v += __shfl_xor_sync(0xffffffffu, v, 4);
            v += __shfl_xor_sync(0xffffffffu, v, 2);
            v += __shfl_xor_sync(0xffffffffu, v, 1);
            float gate = sigf(v + abv);
#pragma unroll
            for (int j = 0; j < 4; j++) acc[e][j] *= gate;
        }
#pragma unroll
        for (int j = 0; j < 4; j++) {
            int c = 4 * tx + j;
            int rot = ((c >> 2) & 15) << 2;
            float* rp = sA + (128 + c) * 64;
#pragma unroll
            for (int g = 0; g < 4; g++) {
                *(float4*)(rp + ((16 * ty + 4 * g + rot) & 63)) =
                    make_float4(acc[4 * g][j], acc[4 * g + 1][j],
                                acc[4 * g + 2][j], acc[4 * g + 3][j]);
            }
        }
    }
    // GEMM3: t3 = silu(m @ cw1 + cb1); w = t3 @ cw2 (folded)
    gemm64(sA + 128 * 64, sW, cw1, 128, 128, acc);
    {
        float wp[16];
#pragma unroll
        for (int e = 0; e < 16; e++) wp[e] = 0.f;
#pragma unroll
        for (int j = 0; j < 4; j++) {
            int c = 4 * tx + j;
            float b = cb1[c], cw = sCw2[c];
#pragma unroll
            for (int e = 0; e < 16; e++) wp[e] += siluf(acc[e][j] + b) * cw;
        }
#pragma unroll
        for (int e = 0; e < 16; e++) {
            float v = wp[e];
            v += __shfl_xor_sync(0xffffffffu, v, 16);
            v += __shfl_xor_sync(0xffffffffu, v, 8);
            v += __shfl_xor_sync(0xffffffffu, v, 4);
            v += __shfl_xor_sync(0xffffffffu, v, 2);
            v += __shfl_xor_sync(0xffffffffu, v, 1);
            if (tx == 0) sWv[16 * ty + e] = v;
        }
    }
    __syncthreads();
    for (int i = tid; i < 192; i += 128) {
        int e = i / 3, d = i - e * 3;
        atomicAdd(&g_aggx[sRow[e] * 3 + d], sCD[i] * sWv[e]);
    }
    for (int i = tid; i < 8192; i += 128) {
        int e = i >> 7, cc = i & 127;
        int rot = ((cc >> 2) & 15) << 2;
        float val = sA[(128 + cc) * 64 + ((e + rot) & 63)];
        atomicAdd(&g_aggh[sRow[e] * HID + cc], val);
    }
}

__global__ void __launch_bounds__(128, 2) k_node(
    int cur, const float* __restrict__ nw1, const float* __restrict__ nb1,
    const float* __restrict__ nw2, const float* __restrict__ nb2,
    const float* __restrict__ vw1, const float* __restrict__ vb1,
    const float* __restrict__ vw2, const float* __restrict__ vb2) {
    extern __shared__ float sm[];
    float* sA = sm;               // 256 rows x 64
    float* sW = sm + 16384;       // 2 x 4096
    float* sS = sm + 24576;       // 64
    float* sVw2 = sm + 24640;     // 128
    const float* hb = cur ? g_hB : g_hA;
    float* hn = cur ? g_hA : g_hB;
    const int tid = threadIdx.x, tx = tid & 31, ty = tid >> 5;
    const int n0 = blockIdx.x * 64;

    if (tid < 128) sVw2[tid] = vw2[tid];
    for (int it = tid; it < 2048; it += 128) {
        int e = it & 63, q = it >> 6;
        int n = n0 + e;
        float4 v = (n < NN) ? *(const float4*)(hb + n * HID + 4 * q)
                            : make_float4(0.f, 0.f, 0.f, 0.f);
        float4 a = (n < NN) ? *(const float4*)(g_aggh + n * HID + 4 * q)
                            : make_float4(0.f, 0.f, 0.f, 0.f);
        int p = (e + ((q & 15) << 2)) & 63;
        int kb = 4 * q * 64;
        sA[kb + p] = v.x; sA[kb + 64 + p] = v.y;
        sA[kb + 128 + p] = v.z; sA[kb + 192 + p] = v.w;
        int kb2 = (128 + 4 * q) * 64;
        sA[kb2 + p] = a.x; sA[kb2 + 64 + p] = a.y;
        sA[kb2 + 128 + p] = a.z; sA[kb2 + 192 + p] = a.w;
    }

    float acc[16][4];
    // velocity MLP: s = silu(h @ vw1 + vb1) @ vw2 + vb2
    gemm64(sA, sW, vw1, 128, 128, acc);
    {
        float sp[16];
#pragma unroll
        for (int e = 0; e < 16; e++) sp[e] = 0.f;
#pragma unroll
        for (int j = 0; j < 4; j++) {
            int c = 4 * tx + j;
            float b = vb1[c], w2 = sVw2[c];
#pragma unroll
            for (int e = 0; e < 16; e++) sp[e] += siluf(acc[e][j] + b) * w2;
        }
        float vb2s = vb2[0];
#pragma unroll
        for (int e = 0; e < 16; e++) {
            float v = sp[e];
            v += __shfl_xor_sync(0xffffffffu, v, 16);
            v += __shfl_xor_sync(0xffffffffu, v, 8);
            v += __shfl_xor_sync(0xffffffffu, v, 4);
            v += __shfl_xor_sync(0xffffffffu, v, 2);
            v += __shfl_xor_sync(0xffffffffu, v, 1);
            if (tx == 0) sS[16 * ty + e] = v + vb2s;
        }
    }
    __syncthreads();
    if (tid < 64) {
        int n = n0 + tid;
        if (n < NN) {
            float cnt = fmaxf(g_cnt[n], 1.f);
            float s = sS[tid];
#pragma unroll
            for (int d = 0; d < 3; d++) {
                float vn = s * g_vel[n * 3 + d];
                g_vel[n * 3 + d] = vn;
                g_x[n * 3 + d] += g_aggx[n * 3 + d] / cnt + vn;
            }
        }
    }
    // node MLP: h = silu([h, aggh] @ nw1 + nb1) @ nw2 + nb2
    gemm64(sA, sW, nw1, 256, 256, acc);
    store_out64(sA, 0, acc, nb1);
    gemm64(sA, sW, nw2, 128, 128, acc);
#pragma unroll
    for (int e = 0; e < 16; e++) {
        int n = n0 + 16 * ty + e;
        if (n < NN) {
            float4 v;
            v.x = acc[e][0] + nb2[4 * tx];
            v.y = acc[e][1] + nb2[4 * tx + 1];
            v.z = acc[e][2] + nb2[4 * tx + 2];
            v.w = acc[e][3] + nb2[4 * tx + 3];
            *(float4*)(hn + n * HID + 4 * tx) = v;
        }
    }
}

__global__ void k_proj(const float* __restrict__ pw, const float* __restrict__ pb,
                       float* __restrict__ out) {
    int i = blockIdx.x * blockDim.x + threadIdx.x;
    if (i < NN * 3) {
        int n = i / 3, p = i - n * 3;
        float s = pb[p];
        const float* hr = g_hA + n * HID;
#pragma unroll 16
        for (int k = 0; k < HID; k++) s += hr[k] * pw[k * 3 + p];
        out[i] = s;
    } else if (i < NN * 6) {
        out[i] = g_x[i - NN * 3];
    } else if (i < NN * 9) {
        out[i] = g_vel[i - NN * 6];
    }
}

extern "C" void kernel_launch(void* const* d_in, const int* in_sizes, int n_in,
                              void* d_out, int out_size) {
    const float* h_in = (const float*)d_in[0];
    const float* x_in = (const float*)d_in[1];
    const float* vel_in = (const float*)d_in[2];
    const float* ea = (const float*)d_in[3];
    const int* edges = (const int*)d_in[4];
    const float* emb_w = (const float*)d_in[5];
    const float* emb_b = (const float*)d_in[6];
    const float* ew1 = (const float*)d_in[7];
    const float* eb1 = (const float*)d_in[8];
    const float* ew2 = (const float*)d_in[9];
    const float* eb2 = (const float*)d_in[10];
    const float* aw = (const float*)d_in[11];
    const float* ab = (const float*)d_in[12];
    const float* nw1 = (const float*)d_in[13];
    const float* nb1 = (const float*)d_in[14];
    const float* nw2 = (const float*)d_in[15];
    const float* nb2 = (const float*)d_in[16];
    const float* cw1 = (const float*)d_in[17];
    const float* cb1 = (const float*)d_in[18];
    const float* cw2 = (const float*)d_in[19];
    const float* vw1 = (const float*)d_in[20];
    const float* vb1 = (const float*)d_in[21];
    const float* vw2 = (const float*)d_in[22];
    const float* vb2 = (const float*)d_in[23];
    const float* pw = (const float*)d_in[24];
    const float* pb = (const float*)d_in[25];

    const int SME = SME_FLOATS * 4;
    const int SMN = SMN_FLOATS * 4;
    cudaFuncSetAttribute(k_edge, cudaFuncAttributeMaxDynamicSharedMemorySize, SME);
    cudaFuncSetAttribute(k_node, cudaFuncAttributeMaxDynamicSharedMemorySize, SMN);

    k_setup<<<5000, 256>>>(h_in, x_in, vel_in, emb_w, emb_b);
    k_count<<<1250, 256>>>(edges);
    for (int i = 0; i < 4; i++) {
        k_zero<<<5000, 256>>>();
        k_edge<<<5000, 128, SME>>>(i & 1, ea, edges,
            ew1 + i * 259 * HID, eb1 + i * HID,
            ew2 + i * HID * HID, eb2 + i * HID,
            aw + i * HID, ab + i,
            cw1 + i * HID * HID, cb1 + i * HID, cw2 + i * HID);
        k_node<<<157, 128, SMN>>>(i & 1,
            nw1 + i * 256 * HID, nb1 + i * HID,
            nw2 + i * HID * HID, nb2 + i * HID,
            vw1 + i * HID * HID, vb1 + i * HID,
            vw2 + i * HID, vb2 + i);
    }
    k_proj<<<(NN * 9 + 255) / 256, 256>>>(pw, pb, (float*)d_out);
}

// round 9
// speedup vs baseline: 1.0274x; 1.0274x over previous
#include <cuda_runtime.h>

#define NN 10000
#define NE 320000
#define HID 128
#define SME_FLOATS 27264
#define SMN_FLOATS 24768

__device__ float g_hA[NN * HID];
__device__ float g_hB[NN * HID];
__device__ float g_x[NN * 3];
__device__ float g_vel[NN * 3];
__device__ float g_aggx[NN * 3];
__device__ float g_aggh[NN * HID];
__device__ float g_cnt[NN];

__device__ __forceinline__ float siluf(float v) {
    return v * __fdividef(1.f, 1.f + __expf(-v));
}
__device__ __forceinline__ float sigf(float v) {
    return __fdividef(1.f, 1.f + __expf(-v));
}

__device__ __forceinline__ unsigned long long pack2(float v) {
    unsigned long long r;
    asm("mov.b64 %0, {%1, %1};" : "=l"(r) : "f"(v));
    return r;
}
__device__ __forceinline__ void unpack2(unsigned long long p, float& a, float& b) {
    asm("mov.b64 {%0, %1}, %2;" : "=f"(a), "=f"(b) : "l"(p));
}
__device__ __forceinline__ void ffma2(unsigned long long& d, unsigned long long a,
                                      unsigned long long b) {
    asm("fma.rn.f32x2 %0, %1, %2, %0;" : "+l"(d) : "l"(a), "l"(b));
}
// vectorized fire-and-forget global reduction (sm_90+)
__device__ __forceinline__ void red4(float* p, float a, float b, float c, float d) {
    asm volatile("red.global.add.v4.f32 [%0], {%1, %2, %3, %4};"
                 :: "l"(p), "f"(a), "f"(b), "f"(c), "f"(d) : "memory");
}

// 64 rows x 128 cols GEMM, 256 threads, 8 edges x 4 cols per thread (f32x2
// pairs along edges). A transposed+swizzled: A[k][e] at
// sA[k*64 + ((e + 4*((k>>2)&15)) & 63)]. W double-buffered through sW
// (2 x 4096 floats) with register prefetch; inner loop software-pipelined
// (depth-1 operand prefetch; chunk-tail over-reads land in adjacent SMEM and
// are never consumed).
__device__ __forceinline__ void gemm64(const float* sA, float* sW,
                                       const float* __restrict__ gW,
                                       int K, int Kpad, float acc[8][4]) {
    const int tid = threadIdx.x, tx = tid & 31, ty = tid >> 5;
    unsigned long long a2[4][4];
#pragma unroll
    for (int p = 0; p < 4; p++)
#pragma unroll
        for (int j = 0; j < 4; j++) a2[p][j] = 0ULL;
    const float4* __restrict__ gW4 = (const float4*)gW;
    const int nch = Kpad >> 5;
    float4 r[4];
#pragma unroll
    for (int i = 0; i < 4; i++) {
        int f = tid + i * 256;
        int rr = f >> 5;
        r[i] = (rr < K) ? gW4[rr * 32 + (f & 31)] : make_float4(0.f, 0.f, 0.f, 0.f);
    }
#pragma unroll
    for (int i = 0; i < 4; i++) ((float4*)sW)[tid + i * 256] = r[i];
    const int b8 = 8 * ty;
    for (int ci = 0; ci < nch; ci++) {
        __syncthreads();
        const int kb = ci << 5;
        const float* buf = sW + ((ci & 1) << 12);
        const float* wp = buf + 4 * tx;
        const bool more = (ci + 1 < nch);
        if (more) {
#pragma unroll
            for (int i = 0; i < 4; i++) {
                int f = tid + i * 256;
                int rr = kb + 32 + (f >> 5);
                r[i] = (rr < K) ? gW4[rr * 32 + (f & 31)]
                                : make_float4(0.f, 0.f, 0.f, 0.f);
            }
        }
        ulonglong2 ca0, ca1;
        float4 cw;
        {
            int rot = ((kb >> 2) & 15) << 2;
            const float* ar = sA + kb * 64;
            ca0 = *(const ulonglong2*)(ar + ((b8 + rot) & 63));
            ca1 = *(const ulonglong2*)(ar + ((b8 + 4 + rot) & 63));
            cw = *(const float4*)(wp);
        }
#pragma unroll 8
        for (int kk = 0; kk < 32; kk++) {
            int k1 = kb + kk + 1;
            int rot = ((k1 >> 2) & 15) << 2;
            const float* ar = sA + k1 * 64;
            ulonglong2 na0 = *(const ulonglong2*)(ar + ((b8 + rot) & 63));
            ulonglong2 na1 = *(const ulonglong2*)(ar + ((b8 + 4 + rot) & 63));
            float4 nw = *(const float4*)(wp + (kk + 1) * 128);
            unsigned long long w0 = pack2(cw.x), w1 = pack2(cw.y);
            unsigned long long w2 = pack2(cw.z), w3 = pack2(cw.w);
            ffma2(a2[0][0], ca0.x, w0); ffma2(a2[0][1], ca0.x, w1);
            ffma2(a2[0][2], ca0.x, w2); ffma2(a2[0][3], ca0.x, w3);
            ffma2(a2[1][0], ca0.y, w0); ffma2(a2[1][1], ca0.y, w1);
            ffma2(a2[1][2], ca0.y, w2); ffma2(a2[1][3], ca0.y, w3);
            ffma2(a2[2][0], ca1.x, w0); ffma2(a2[2][1], ca1.x, w1);
            ffma2(a2[2][2], ca1.x, w2); ffma2(a2[2][3], ca1.x, w3);
            ffma2(a2[3][0], ca1.y, w0); ffma2(a2[3][1], ca1.y, w1);
            ffma2(a2[3][2], ca1.y, w2); ffma2(a2[3][3], ca1.y, w3);
            ca0 = na0; ca1 = na1; cw = nw;
        }
        if (more) {
            float* nb = sW + (((ci + 1) & 1) << 12);
#pragma unroll
            for (int i = 0; i < 4; i++) ((float4*)nb)[tid + i * 256] = r[i];
        }
    }
#pragma unroll
    for (int p = 0; p < 4; p++)
#pragma unroll
        for (int j = 0; j < 4; j++) unpack2(a2[p][j], acc[2 * p][j], acc[2 * p + 1][j]);
    __syncthreads();
}

// Write acc (+bias, silu) transposed into sA rows baseRow..baseRow+127.
__device__ __forceinline__ void store_out64(float* sA, int baseRow, float acc[8][4],
                                            const float* __restrict__ bias) {
    const int tid = threadIdx.x, tx = tid & 31, ty = tid >> 5;
#pragma unroll
    for (int j = 0; j < 4; j++) {
        int c = 4 * tx + j;
        float b = bias[c];
        int rot = ((c >> 2) & 15) << 2;
        float* rp = sA + (baseRow + c) * 64;
        float4 v0, v1;
        v0.x = siluf(acc[0][j] + b); v0.y = siluf(acc[1][j] + b);
        v0.z = siluf(acc[2][j] + b); v0.w = siluf(acc[3][j] + b);
        v1.x = siluf(acc[4][j] + b); v1.y = siluf(acc[5][j] + b);
        v1.z = siluf(acc[6][j] + b); v1.w = siluf(acc[7][j] + b);
        *(float4*)(rp + ((8 * ty + rot) & 63)) = v0;
        *(float4*)(rp + ((8 * ty + 4 + rot) & 63)) = v1;
    }
}

__global__ void k_setup(const float* __restrict__ h_in, const float* __restrict__ x_in,
                        const float* __restrict__ vel_in, const float* __restrict__ emb_w,
                        const float* __restrict__ emb_b) {
    int i = blockIdx.x * blockDim.x + threadIdx.x;
    if (i < NN * 3) { g_x[i] = x_in[i]; g_vel[i] = vel_in[i]; }
    if (i < NN) g_cnt[i] = 0.f;
    if (i < NN * HID) {
        int n = i >> 7, c = i & 127;
        float s = emb_b[c];
#pragma unroll
        for (int k = 0; k < 6; k++) s += h_in[n * 6 + k] * emb_w[k * HID + c];
        g_hA[i] = s;
    }
}

__global__ void k_count(const int* __restrict__ edges) {
    int e = blockIdx.x * blockDim.x + threadIdx.x;
    if (e < NE) atomicAdd(&g_cnt[edges[e]], 1.f);
}

__global__ void k_zero() {
    int i = blockIdx.x * blockDim.x + threadIdx.x;
    if (i < NN * 3) g_aggx[i] = 0.f;
    if (i < NN * HID) g_aggh[i] = 0.f;
}

__global__ void __launch_bounds__(256, 2) k_edge(
    int cur, const float* __restrict__ ea, const int* __restrict__ edges,
    const float* __restrict__ ew1, const float* __restrict__ eb1,
    const float* __restrict__ ew2, const float* __restrict__ eb2,
    const float* __restrict__ aw, const float* __restrict__ ab,
    const float* __restrict__ cw1, const float* __restrict__ cb1,
    const float* __restrict__ cw2) {
    extern __shared__ float sm[];
    float* sA = sm;                    // 288 rows x 64
    float* sW = sm + 18432;            // 2 x 4096 (double buffer)
    float* sCD = sm + 26624;           // 192
    float* sWv = sm + 26816;           // 64
    float* sAw = sm + 26880;           // 128
    float* sCw2 = sm + 27008;          // 128
    int* sRow = (int*)(sm + 27136);    // 64
    int* sCol = (int*)(sm + 27200);    // 64
    const float* hb = cur ? g_hB : g_hA;
    const int tid = threadIdx.x, tx = tid & 31, ty = tid >> 5;
    const int e0 = blockIdx.x * 64;

    if (tid < 128) { sAw[tid] = aw[tid]; sCw2[tid] = cw2[tid]; }
    if (tid < 64) {
        int e = e0 + tid;
        int r = edges[e], c = edges[NE + e];
        sRow[tid] = r; sCol[tid] = c;
        float dx = g_x[r * 3] - g_x[c * 3];
        float dy = g_x[r * 3 + 1] - g_x[c * 3 + 1];
        float dz = g_x[r * 3 + 2] - g_x[c * 3 + 2];
        sCD[tid * 3] = dx; sCD[tid * 3 + 1] = dy; sCD[tid * 3 + 2] = dz;
        sA[256 * 64 + tid] = dx * dx + dy * dy + dz * dz;  // rot=0 rows 256..258
        sA[257 * 64 + tid] = ea[e * 2];
        sA[258 * 64 + tid] = ea[e * 2 + 1];
    }
    for (int i = tid; i < 29 * 64; i += 256) sA[259 * 64 + i] = 0.f;
    __syncthreads();
    for (int it = tid; it < 2048; it += 256) {  // h[row] -> rows 0..127
        int e = it & 63, q = it >> 6;
        float4 v = *(const float4*)(hb + sRow[e] * HID + 4 * q);
        int p = (e + ((q & 15) << 2)) & 63;
        int kb = 4 * q * 64;
        sA[kb + p] = v.x; sA[kb + 64 + p] = v.y;
        sA[kb + 128 + p] = v.z; sA[kb + 192 + p] = v.w;
    }
    for (int it = tid; it < 2048; it += 256) {  // h[col] -> rows 128..255
        int e = it & 63, q = it >> 6;
        float4 v = *(const float4*)(hb + sCol[e] * HID + 4 * q);
        int p = (e + ((q & 15) << 2)) & 63;
        int kb = (128 + 4 * q) * 64;
        sA[kb + p] = v.x; sA[kb + 64 + p] = v.y;
        sA[kb + 128 + p] = v.z; sA[kb + 192 + p] = v.w;
    }

    float acc[8][4];
    // GEMM1: t1 = silu(e_in @ ew1 + eb1) -> rows 0..127
    gemm64(sA, sW, ew1, 259, 288, acc);
    store_out64(sA, 0, acc, eb1);
    // GEMM2: m = silu(t1 @ ew2 + eb2), attention gate fused -> rows 128..255
    gemm64(sA, sW, ew2, 128, 128, acc);
    {
        float mv[8][4];
        float attp[8] = {0, 0, 0, 0, 0, 0, 0, 0};
#pragma unroll
        for (int j = 0; j < 4; j++) {
            int c = 4 * tx + j;
            float b = eb2[c], wA = sAw[c];
#pragma unroll
            for (int e = 0; e < 8; e++) {
                mv[e][j] = siluf(acc[e][j] + b);
                attp[e] += mv[e][j] * wA;
            }
        }
        float abv = ab[0];
#pragma unroll
        for (int e = 0; e < 8; e++) {
            float v = attp[e];
            v += __shfl_xor_sync(0xffffffffu, v, 16);
            v += __shfl_xor_sync(0xffffffffu, v, 8);
            v += __shfl_xor_sync(0xffffffffu, v, 4);
            v += __shfl_xor_sync(0xffffffffu, v, 2);
            v += __shfl_xor_sync(0xffffffffu, v, 1);
            float gate = sigf(v + abv);
#pragma unroll
            for (int j = 0; j < 4; j++) mv[e][j] *= gate;
        }
#pragma unroll
        for (int j = 0; j < 4; j++) {
            int c = 4 * tx + j;
            int rot = ((c >> 2) & 15) << 2;
            float* rp = sA + (128 + c) * 64;
            *(float4*)(rp + ((8 * ty + rot) & 63)) =
                make_float4(mv[0][j], mv[1][j], mv[2][j], mv[3][j]);
            *(float4*)(rp + ((8 * ty + 4 + rot) & 63)) =
                make_float4(mv[4][j], mv[5][j], mv[6][j], mv[7][j]);
        }
        // agg_h: vectorized red straight from registers (cols 4tx..4tx+3 of
        // edge 8ty+e are float4-contiguous in g_aggh). Fire-and-forget;
        // drains under GEMM3.
#pragma unroll
        for (int e = 0; e < 8; e++) {
            int ge = sRow[8 * ty + e];
            red4(&g_aggh[ge * HID + 4 * tx], mv[e][0], mv[e][1], mv[e][2], mv[e][3]);
        }
    }
    // GEMM3: t3 = silu(m @ cw1 + cb1); w = t3 @ cw2 (folded)
    gemm64(sA + 128 * 64, sW, cw1, 128, 128, acc);
    {
        float wp[8] = {0, 0, 0, 0, 0, 0, 0, 0};
#pragma unroll
        for (int j = 0; j < 4; j++) {
            int c = 4 * tx + j;
            float b = cb1[c], cw = sCw2[c];
#pragma unroll
            for (int e = 0; e < 8; e++) wp[e] += siluf(acc[e][j] + b) * cw;
        }
#pragma unroll
        for (int e = 0; e < 8; e++) {
            float v = wp[e];
            v += __shfl_xor_sync(0xffffffffu, v, 16);
            v += __shfl_xor_sync(0xffffffffu, v, 8);
            v += __shfl_xor_sync(0xffffffffu, v, 4);
            v += __shfl_xor_sync(0xffffffffu, v, 2);
            v += __shfl_xor_sync(0xffffffffu, v, 1);
            if (tx == 0) sWv[8 * ty + e] = v;
        }
    }
    __syncthreads();
    if (tid < 192) {
        int e = tid / 3, d = tid - e * 3;
        atomicAdd(&g_aggx[sRow[e] * 3 + d], sCD[tid] * sWv[e]);
    }
}

__global__ void __launch_bounds__(256, 2) k_node(
    int cur, const float* __restrict__ nw1, const float* __restrict__ nb1,
    const float* __restrict__ nw2, const float* __restrict__ nb2,
    const float* __restrict__ vw1, const float* __restrict__ vb1,
    const float* __restrict__ vw2, const float* __restrict__ vb2) {
    extern __shared__ float sm[];
    float* sA = sm;               // 256 rows x 64
    float* sW = sm + 16384;       // 2 x 4096
    float* sS = sm + 24576;       // 64
    float* sVw2 = sm + 24640;     // 128
    const float* hb = cur ? g_hB : g_hA;
    float* hn = cur ? g_hA : g_hB;
    const int tid = threadIdx.x, tx = tid & 31, ty = tid >> 5;
    const int n0 = blockIdx.x * 64;

    if (tid < 128) sVw2[tid] = vw2[tid];
    for (int it = tid; it < 2048; it += 256) {
        int e = it & 63, q = it >> 6;
        int n = n0 + e;
        float4 v = (n < NN) ? *(const float4*)(hb + n * HID + 4 * q)
                            : make_float4(0.f, 0.f, 0.f, 0.f);
        float4 a = (n < NN) ? *(const float4*)(g_aggh + n * HID + 4 * q)
                            : make_float4(0.f, 0.f, 0.f, 0.f);
        int p = (e + ((q & 15) << 2)) & 63;
        int kb = 4 * q * 64;
        sA[kb + p] = v.x; sA[kb + 64 + p] = v.y;
        sA[kb + 128 + p] = v.z; sA[kb + 192 + p] = v.w;
        int kb2 = (128 + 4 * q) * 64;
        sA[kb2 + p] = a.x; sA[kb2 + 64 + p] = a.y;
        sA[kb2 + 128 + p] = a.z; sA[kb2 + 192 + p] = a.w;
    }

    float acc[8][4];
    // velocity MLP: s = silu(h @ vw1 + vb1) @ vw2 + vb2
    gemm64(sA, sW, vw1, 128, 128, acc);
    {
        float sp[8] = {0, 0, 0, 0, 0, 0, 0, 0};
#pragma unroll
        for (int j = 0; j < 4; j++) {
            int c = 4 * tx + j;
            float b = vb1[c], w2 = sVw2[c];
#pragma unroll
            for (int e = 0; e < 8; e++) sp[e] += siluf(acc[e][j] + b) * w2;
        }
        float vb2s = vb2[0];
#pragma unroll
        for (int e = 0; e < 8; e++) {
            float v = sp[e];
            v += __shfl_xor_sync(0xffffffffu, v, 16);
            v += __shfl_xor_sync(0xffffffffu, v, 8);
            v += __shfl_xor_sync(0xffffffffu, v, 4);
            v += __shfl_xor_sync(0xffffffffu, v, 2);
            v += __shfl_xor_sync(0xffffffffu, v, 1);
            if (tx == 0) sS[8 * ty + e] = v + vb2s;
        }
    }
    __syncthreads();
    if (tid < 64) {
        int n = n0 + tid;
        if (n < NN) {
            float cnt = fmaxf(g_cnt[n], 1.f);
            float s = sS[tid];
#pragma unroll
            for (int d = 0; d < 3; d++) {
                float vn = s * g_vel[n * 3 + d];
                g_vel[n * 3 + d] = vn;
                g_x[n * 3 + d] += g_aggx[n * 3 + d] / cnt + vn;
            }
        }
    }
    // node MLP: h = silu([h, aggh] @ nw1 + nb1) @ nw2 + nb2
    gemm64(sA, sW, nw1, 256, 256, acc);
    store_out64(sA, 0, acc, nb1);
    gemm64(sA, sW, nw2, 128, 128, acc);
#pragma unroll
    for (int e = 0; e < 8; e++) {
        int n = n0 + 8 * ty + e;
        if (n < NN) {
            float4 v;
            v.x = acc[e][0] + nb2[4 * tx];
            v.y = acc[e][1] + nb2[4 * tx + 1];
            v.z = acc[e][2] + nb2[4 * tx + 2];
            v.w = acc[e][3] + nb2[4 * tx + 3];
            *(float4*)(hn + n * HID + 4 * tx) = v;
        }
    }
}

__global__ void k_proj(const float* __restrict__ pw, const float* __restrict__ pb,
                       float* __restrict__ out) {
    int i = blockIdx.x * blockDim.x + threadIdx.x;
    if (i < NN * 3) {
        int n = i / 3, p = i - n * 3;
        float s = pb[p];
        const float* hr = g_hA + n * HID;
#pragma unroll 16
        for (int k = 0; k < HID; k++) s += hr[k] * pw[k * 3 + p];
        out[i] = s;
    } else if (i < NN * 6) {
        out[i] = g_x[i - NN * 3];
    } else if (i < NN * 9) {
        out[i] = g_vel[i - NN * 6];
    }
}

extern "C" void kernel_launch(void* const* d_in, const int* in_sizes, int n_in,
                              void* d_out, int out_size) {
    const float* h_in = (const float*)d_in[0];
    const float* x_in = (const float*)d_in[1];
    const float* vel_in = (const float*)d_in[2];
    const float* ea = (const float*)d_in[3];
    const int* edges = (const int*)d_in[4];
    const float* emb_w = (const float*)d_in[5];
    const float* emb_b = (const float*)d_in[6];
    const float* ew1 = (const float*)d_in[7];
    const float* eb1 = (const float*)d_in[8];
    const float* ew2 = (const float*)d_in[9];
    const float* eb2 = (const float*)d_in[10];
    const float* aw = (const float*)d_in[11];
    const float* ab = (const float*)d_in[12];
    const float* nw1 = (const float*)d_in[13];
    const float* nb1 = (const float*)d_in[14];
    const float* nw2 = (const float*)d_in[15];
    const float* nb2 = (const float*)d_in[16];
    const float* cw1 = (const float*)d_in[17];
    const float* cb1 = (const float*)d_in[18];
    const float* cw2 = (const float*)d_in[19];
    const float* vw1 = (const float*)d_in[20];
    const float* vb1 = (const float*)d_in[21];
    const float* vw2 = (const float*)d_in[22];
    const float* vb2 = (const float*)d_in[23];
    const float* pw = (const float*)d_in[24];
    const float* pb = (const float*)d_in[25];

    const int SME = SME_FLOATS * 4;
    const int SMN = SMN_FLOATS * 4;
    cudaFuncSetAttribute(k_edge, cudaFuncAttributeMaxDynamicSharedMemorySize, SME);
    cudaFuncSetAttribute(k_node, cudaFuncAttributeMaxDynamicSharedMemorySize, SMN);

    k_setup<<<5000, 256>>>(h_in, x_in, vel_in, emb_w, emb_b);
    k_count<<<1250, 256>>>(edges);
    for (int i = 0; i < 4; i++) {
        k_zero<<<5000, 256>>>();
        k_edge<<<5000, 256, SME>>>(i & 1, ea, edges,
            ew1 + i * 259 * HID, eb1 + i * HID,
            ew2 + i * HID * HID, eb2 + i * HID,
            aw + i * HID, ab + i,
            cw1 + i * HID * HID, cb1 + i * HID, cw2 + i * HID);
        k_node<<<157, 256, SMN>>>(i & 1,
            nw1 + i * 256 * HID, nb1 + i * HID,
            nw2 + i * HID * HID, nb2 + i * HID,
            vw1 + i * HID * HID, vb1 + i * HID,
            vw2 + i * HID, vb2 + i);
    }
    k_proj<<<(NN * 9 + 255) / 256, 256>>>(pw, pb, (float*)d_out);
}